// round 16
// baseline (speedup 1.0000x reference)
#include <cuda_runtime.h>
#include <cuda_fp16.h>
#include <math.h>

#define NHID   1024
#define NLAY   4
#define NST    64
#define TSTEPS 101
#define NUNITS (NLAY*NHID)            // 4096
#define ROWLEN 2048                   // packed row: [Whh(1024) | Wih(1024)]
#define NPHASE (TSTEPS + NLAY - 1)    // 104 wavefront phases
#define NCTA     148
#define NWORK    147
#define NTHREADS 896                  // 28 warps
#define NSLOTS 27                     // warps 0..26 get an 8KB Whh-half smem slot
#define S_W_HALFS (NSLOTS*4*ROWLEN/2)        // 27*4096 = 110592 halfs = 221184 B
#define S_X_OFF   S_W_HALFS                  // x region: [h3|h2|h1|h0|z/0] = 5120 halfs
#define SMEM_TOTAL ((S_X_OFF + 5120) * 2)    // 231424 bytes (same as R4/R15)

#define OUT_STATES 0
#define OUT_PROBS  (TSTEPS*NST)              // 6464
#define OUT_SAMP   (OUT_PROBS + TSTEPS*2)    // 6666

#define H2(v,k) (((const __half2*)&(v))[k])

// ---- persistent device state (round-4 layout) ----
__device__ __align__(128) __half g_wpack[(size_t)NUNITS * 4 * ROWLEN]; // 64 MB
__device__ float  g_bias[NLAY*4*NHID];                                 // bih + bhh
__device__ __align__(16) __half g_ws[NST*NHID];                        // fp16 state head
__device__ __align__(16) __half g_hout[2][NLAY][NHID];                 // double-buffered hidden
__device__ __align__(128) unsigned g_arrive;                           // barrier counter

// ---- prep + init fused (round-15 verbatim) ----
__global__ void k_prep(const float* __restrict__ wih, const float* __restrict__ whh,
                       const float* __restrict__ bih, const float* __restrict__ bhh,
                       const float* __restrict__ ws, float* __restrict__ dout) {
    int row = blockIdx.x;                 // 0..16383 == u*4+g
    int u = row >> 2, g = row & 3;
    int l = u >> 10, j = u & 1023;
    size_t src = ((size_t)l*4096 + g*1024 + j) * 1024;
    __half* dst = g_wpack + (size_t)row * ROWLEN;
    int k = threadIdx.x * 4;
    float4 hv = *(const float4*)(whh + src + k);
    __half2* d0 = (__half2*)(dst + k);
    d0[0] = __floats2half2_rn(hv.x, hv.y);
    d0[1] = __floats2half2_rn(hv.z, hv.w);
    float4 iv = *(const float4*)(wih + src + k);
    __half2* d1 = (__half2*)(dst + 1024 + k);
    d1[0] = __floats2half2_rn(iv.x, iv.y);
    d1[1] = __floats2half2_rn(iv.z, iv.w);

    int gi = blockIdx.x * blockDim.x + threadIdx.x;
    if (gi < NLAY*4*NHID)  g_bias[gi] = bih[gi] + bhh[gi];
    if (gi < NST*NHID)     g_ws[gi] = __float2half_rn(ws[gi]);
    if (gi < 2*NLAY*NHID)  ((__half*)g_hout)[gi] = __float2half(0.f);
    if (gi < TSTEPS)       dout[OUT_SAMP + gi] = (gi == TSTEPS-1) ? 1.f : 0.f;
    if (gi == 0) {
        g_arrive = 0;
        dout[OUT_PROBS + 2*(TSTEPS-1) + 0] = 0.f;   // forced last-step probs
        dout[OUT_PROBS + 2*(TSTEPS-1) + 1] = 1.f;
    }
}

// ---- helpers (round-4 verbatim) ----
__device__ __forceinline__ float hdot16(uint4 wa, uint4 wb, uint4 xa, uint4 xb) {
    __half2 h = __hmul2(H2(wa,0), H2(xa,0));
    h = __hfma2(H2(wa,1), H2(xa,1), h);
    h = __hfma2(H2(wa,2), H2(xa,2), h);
    h = __hfma2(H2(wa,3), H2(xa,3), h);
    h = __hfma2(H2(wb,0), H2(xb,0), h);
    h = __hfma2(H2(wb,1), H2(xb,1), h);
    h = __hfma2(H2(wb,2), H2(xb,2), h);
    h = __hfma2(H2(wb,3), H2(xb,3), h);
    return __low2float(h) + __high2float(h);
}

__device__ __forceinline__ float hdot8(uint4 w, uint4 x) {
    __half2 a = __hmul2(H2(w,0), H2(x,0));
    a = __hfma2(H2(w,1), H2(x,1), a);
    a = __hfma2(H2(w,2), H2(x,2), a);
    a = __hfma2(H2(w,3), H2(x,3), a);
    return __low2float(a) + __high2float(a);
}

__device__ __forceinline__ float wredsum(float v) {
    v += __shfl_xor_sync(0xffffffffu, v, 16);
    v += __shfl_xor_sync(0xffffffffu, v, 8);
    v += __shfl_xor_sync(0xffffffffu, v, 4);
    v += __shfl_xor_sync(0xffffffffu, v, 2);
    v += __shfl_xor_sync(0xffffffffu, v, 1);
    return v;
}

__device__ __forceinline__ float sigf(float x) {
    return __fdividef(1.f, 1.f + __expf(-x));
}
__device__ __forceinline__ float tanhfast(float x) {
    return 2.f * sigf(2.f * x) - 1.f;
}

// round-4 gate dots, 16-term fp16 windows. block (g,cp): w + g*GS + cp*64.
template <int NPAIR, int GS, bool RES, bool PF>
__device__ __forceinline__ void gatedot4(const uint4* __restrict__ w,
                                         const uint4* __restrict__ xs, int lane,
                                         const uint4* pw, float* a)
{
#pragma unroll
    for (int cp = 0; cp < NPAIR; ++cp) {
        uint4 xa = xs[cp*64 + lane];
        uint4 xb = xs[cp*64 + 32 + lane];
#pragma unroll
        for (int g = 0; g < 4; ++g) {
            uint4 wa;
            if (PF && cp == 0) wa = pw[g];
            else wa = RES ? w[g*GS + cp*64 + lane] : __ldg(w + g*GS + cp*64 + lane);
            uint4 wb = RES ? w[g*GS + cp*64 + 32 + lane]
                           : __ldg(w + g*GS + cp*64 + 32 + lane);
            a[g] += hdot16(wa, wb, xa, xb);
        }
    }
}

// ---- main persistent kernel: 104 wavefront phases ----
__global__ void __launch_bounds__(NTHREADS, 1) k_lstm(
    const float* __restrict__ z,
    const float* __restrict__ bs,
    const float* __restrict__ wp,
    const float* __restrict__ bp,
    float* __restrict__ dout)
{
    extern __shared__ __align__(16) __half smem[];
    __half* s_x = smem + S_X_OFF;

    const int tid  = threadIdx.x;
    const int bid  = blockIdx.x;
    const int wid  = tid >> 5;
    const int lane = tid & 31;
    const bool is_head = (bid == NCTA - 1);

    int u = is_head ? -1 : (wid * NWORK + bid);      // permanent unit ownership
    if (u >= NUNITS) u = -1;
    const int l = (u >= 0) ? (u >> 10) : 0;
    const int j = (u >= 0) ? (u & 1023) : 0;
    const uint4* wr4 = (const uint4*)(g_wpack + (size_t)((u >= 0) ? u : 0) * 4 * ROWLEN);

    // uniform half-residency: warps 0..26 keep their Whh half (chunks 0-1) in smem
    const bool has_slot = (u >= 0) && (wid < NSLOTS);

    if (has_slot) {
        uint4* dst = (uint4*)smem + wid * 512;
#pragma unroll
        for (int g = 0; g < 4; ++g)
            for (int i = lane; i < 128; i += 32) dst[g*128 + i] = wr4[g*256 + i];
    }
    const uint4* wsm4 = (const uint4*)smem + ((wid < NSLOTS) ? wid : 0) * 512;
    __syncthreads();

    // phase-invariant per-warp state
    float b0 = 0.f, b1 = 0.f, b2 = 0.f, b3 = 0.f;
    if (u >= 0) {
        const float* bl = g_bias + l*4096 + j;
        b0 = bl[0]; b1 = bl[1024]; b2 = bl[2048]; b3 = bl[3072];
    }
    float c = 0.f;

    // prefetch: first LDG chunk of the steady-state path
    //   has_slot & l>0 : chunk 2 (start of the Wih/LDG half)
    //   no slot (wid27): chunk 0 (full-LDG path)
    uint4 pw[4];
    auto load_pw = [&]() {
        if (u >= 0 && l != 0) {
            if (has_slot) {
#pragma unroll
                for (int g = 0; g < 4; ++g) pw[g] = __ldg(wr4 + 128 + g*256 + lane);
            } else {
#pragma unroll
                for (int g = 0; g < 4; ++g) pw[g] = __ldg(wr4 + g*256 + lane);
            }
        }
    };
    load_pw();

    for (int p = 0; p < NPHASE; ++p) {
        const int rb = (p & 1) ^ 1;
        const int wbuf = p & 1;

        // stage x: [h3|h2|h1|h0], z/zeros at p<=1 (round-4 verbatim)
        if (tid < 512) {
            int chunk = tid >> 7, k = tid & 127;
            ((uint4*)s_x)[tid] = ((const uint4*)&g_hout[rb][3 - chunk][0])[k];
        } else if (p <= 1 && tid < 640) {
            int k = tid - 512;
            uint4 v;
            if (p == 0) {
                float4 z0 = ((const float4*)z)[k*2];
                float4 z1 = ((const float4*)z)[k*2 + 1];
                __half2 h0 = __floats2half2_rn(z0.x, z0.y);
                __half2 h1 = __floats2half2_rn(z0.z, z0.w);
                __half2 h2 = __floats2half2_rn(z1.x, z1.y);
                __half2 h3 = __floats2half2_rn(z1.z, z1.w);
                v.x = *(unsigned*)&h0; v.y = *(unsigned*)&h1;
                v.z = *(unsigned*)&h2; v.w = *(unsigned*)&h3;
            } else { v.x = v.y = v.z = v.w = 0u; }
            ((uint4*)s_x)[tid] = v;
        }
        __syncthreads();

        if (u >= 0) {
            const int t = p - l;
            if (t >= 0 && t < TSTEPS) {
                float a[4] = {0.f, 0.f, 0.f, 0.f};
                const uint4* xs = (const uint4*)s_x + (3 - l) * 128;
                if (l == 0) {
                    if (t == 0)            // gates = Wih * z (h==0); pw untouched
                        gatedot4<2,256,false,false>(wr4 + 128, (const uint4*)s_x + 512, lane, pw, a);
                    else if (has_slot)     // whole t>0 working set is the smem Whh half
                        gatedot4<2,128,true,false>(wsm4, xs, lane, pw, a);
                    else
                        gatedot4<2,256,false,false>(wr4, xs, lane, pw, a);
                } else {
                    if (has_slot) {
                        // order-preserving: chunks 0-1 from smem, then 2-3 via LDG (pw = chunk 2)
                        gatedot4<2,128,true,false>(wsm4, xs, lane, pw, a);
                        gatedot4<2,256,false,true>(wr4 + 128, xs + 128, lane, pw, a);
                    } else {
                        gatedot4<4,256,false,true>(wr4, xs, lane, pw, a);
                    }
                }
                float gi = wredsum(a[0]) + b0;
                float gf = wredsum(a[1]) + b1;
                float gg = wredsum(a[2]) + b2;
                float go = wredsum(a[3]) + b3;
                c = sigf(gf) * c + sigf(gi) * tanhfast(gg);
                float hn = sigf(go) * tanhfast(c);
                if (lane == 0) g_hout[wbuf][l][j] = __float2half_rn(hn);
            }
        } else if (is_head && p >= 4) {
            const int t = p - 4;                       // h_3(t) == s_x[0..127] uint4
            const uint4* xs = (const uint4*)s_x;
            for (int r = wid; r < NST + 2; r += 28) {
                if (r < NST) {
                    const uint4* wrow = (const uint4*)(g_ws + r*NHID);
                    float a = 0.f;
#pragma unroll
                    for (int cch = 0; cch < 4; ++cch)
                        a += hdot8(__ldg(wrow + cch*32 + lane), xs[cch*32 + lane]);
                    a = wredsum(a);
                    if (lane == 0) dout[OUT_STATES + t*NST + r] = a + bs[r];
                } else if (r == NST) {
                    float a0 = 0.f, a1 = 0.f;
#pragma unroll
                    for (int cch = 0; cch < 4; ++cch) {
                        uint4 xv = xs[cch*32 + lane];
                        float2 x0 = __half22float2(H2(xv,0));
                        float2 x1 = __half22float2(H2(xv,1));
                        float2 x2 = __half22float2(H2(xv,2));
                        float2 x3 = __half22float2(H2(xv,3));
                        const float4* p0 = (const float4*)(wp) + cch*64 + lane*2;
                        const float4* p1 = (const float4*)(wp + NHID) + cch*64 + lane*2;
                        float4 wA = p0[0], wB = p0[1];
                        float4 wC = p1[0], wD = p1[1];
                        a0 += wA.x*x0.x + wA.y*x0.y + wA.z*x1.x + wA.w*x1.y
                            + wB.x*x2.x + wB.y*x2.y + wB.z*x3.x + wB.w*x3.y;
                        a1 += wC.x*x0.x + wC.y*x0.y + wC.z*x1.x + wC.w*x1.y
                            + wD.x*x2.x + wD.y*x2.y + wD.z*x3.x + wD.w*x3.y;
                    }
                    a0 = wredsum(a0); a1 = wredsum(a1);
                    if (lane == 0) {
                        float l0v = a0 + bp[0] + 1.0f;   // P_BIAS on logit 0
                        float l1v = a1 + bp[1];
                        float m  = fmaxf(l0v, l1v);
                        float e0 = __expf(l0v - m), e1 = __expf(l1v - m);
                        float inv = 1.f / (e0 + e1);
                        dout[OUT_PROBS + t*2 + 0] = e0 * inv;
                        dout[OUT_PROBS + t*2 + 1] = e1 * inv;
                    }
                }
            }
        }

        // grid barrier (round-4 verbatim: tid0-only arrive + poll, pw prefetch in wait)
        __syncthreads();
        if (tid == 0)
            asm volatile("red.release.gpu.global.add.u32 [%0], %1;"
                         :: "l"(&g_arrive), "r"(1u) : "memory");
        load_pw();                       // phase-invariant; fills during the poll
        if (tid == 0) {
            unsigned target = (unsigned)(p + 1) * NCTA, v;
            do {
                asm volatile("ld.acquire.gpu.global.u32 %0, [%1];"
                             : "=r"(v) : "l"(&g_arrive) : "memory");
            } while (v < target);
        }
        __syncthreads();
    }

    // epilogue: heads for t = 100 (h_3(100) in buffer (NPHASE-1)&1 = 1)
    if (is_head) {
        const uint4* xs = (const uint4*)(&g_hout[1][3][0]);
        for (int r = wid; r < NST; r += 28) {
            const uint4* wrow = (const uint4*)(g_ws + r*NHID);
            float a = 0.f;
#pragma unroll
            for (int cch = 0; cch < 4; ++cch)
                a += hdot8(__ldg(wrow + cch*32 + lane), xs[cch*32 + lane]);
            a = wredsum(a);
            if (lane == 0) dout[OUT_STATES + (TSTEPS-1)*NST + r] = a + bs[r];
        }
    }
}

extern "C" void kernel_launch(void* const* d_in, const int* in_sizes, int n_in,
                              void* d_out, int out_size) {
    (void)in_sizes; (void)n_in; (void)out_size;
    const float* z   = (const float*)d_in[0];
    const float* wih = (const float*)d_in[1];
    const float* whh = (const float*)d_in[2];
    const float* bih = (const float*)d_in[3];
    const float* bhh = (const float*)d_in[4];
    const float* ws  = (const float*)d_in[5];
    const float* bs  = (const float*)d_in[6];
    const float* wp  = (const float*)d_in[7];
    const float* bp  = (const float*)d_in[8];
    float* out = (float*)d_out;

    cudaFuncSetAttribute(k_lstm, cudaFuncAttributeMaxDynamicSharedMemorySize, SMEM_TOTAL);

    k_prep<<<NUNITS*4, 256>>>(wih, whh, bih, bhh, ws, out);
    k_lstm<<<NCTA, NTHREADS, SMEM_TOTAL>>>(z, bs, wp, bp, out);
}

// round 17
// speedup vs baseline: 1.0415x; 1.0415x over previous
#include <cuda_runtime.h>
#include <cuda_fp16.h>
#include <math.h>

#define NHID   1024
#define NLAY   4
#define NST    64
#define TSTEPS 101
#define NUNITS (NLAY*NHID)            // 4096
#define ROWLEN 2048                   // packed row: [Whh(1024) | Wih(1024)]
#define NPHASE (TSTEPS + NLAY - 1)    // 104 wavefront phases
#define NCTA     148
#define NWORK    147
#define NTHREADS 896                  // 28 warps
#define RES_LO 7                      // full-resident warps [7,19] (round-4/15 proven)
#define RES_HI 19
#define S_W_HALFS (4096 + 13*4*ROWLEN)       // 110592 halfs = 221184 B
#define S_X_OFF   S_W_HALFS                  // x region: [h3|h2|h1|h0|z/0] = 5120 halfs
#define SMEM_TOTAL ((S_X_OFF + 5120) * 2)    // 231424 bytes

#define OUT_STATES 0
#define OUT_PROBS  (TSTEPS*NST)              // 6464
#define OUT_SAMP   (OUT_PROBS + TSTEPS*2)    // 6666

#define H2(v,k) (((const __half2*)&(v))[k])

// ---- persistent device state (round-15 layout) ----
__device__ __align__(128) __half g_wpack[(size_t)NUNITS * 4 * ROWLEN]; // 64 MB
__device__ float  g_bias[NLAY*4*NHID];                                 // bih + bhh
__device__ __align__(16) __half g_ws[NST*NHID];                        // fp16 state head
__device__ __align__(16) __half g_hout[2][NLAY][NHID];                 // double-buffered hidden
__device__ __align__(128) unsigned g_arrive;                           // barrier counter

// ---- prep + init fused (round-15 verbatim) ----
__global__ void k_prep(const float* __restrict__ wih, const float* __restrict__ whh,
                       const float* __restrict__ bih, const float* __restrict__ bhh,
                       const float* __restrict__ ws, float* __restrict__ dout) {
    int row = blockIdx.x;                 // 0..16383 == u*4+g
    int u = row >> 2, g = row & 3;
    int l = u >> 10, j = u & 1023;
    size_t src = ((size_t)l*4096 + g*1024 + j) * 1024;
    __half* dst = g_wpack + (size_t)row * ROWLEN;
    int k = threadIdx.x * 4;
    float4 hv = *(const float4*)(whh + src + k);
    __half2* d0 = (__half2*)(dst + k);
    d0[0] = __floats2half2_rn(hv.x, hv.y);
    d0[1] = __floats2half2_rn(hv.z, hv.w);
    float4 iv = *(const float4*)(wih + src + k);
    __half2* d1 = (__half2*)(dst + 1024 + k);
    d1[0] = __floats2half2_rn(iv.x, iv.y);
    d1[1] = __floats2half2_rn(iv.z, iv.w);

    int gi = blockIdx.x * blockDim.x + threadIdx.x;
    if (gi < NLAY*4*NHID)  g_bias[gi] = bih[gi] + bhh[gi];
    if (gi < NST*NHID)     g_ws[gi] = __float2half_rn(ws[gi]);
    if (gi < 2*NLAY*NHID)  ((__half*)g_hout)[gi] = __float2half(0.f);
    if (gi < TSTEPS)       dout[OUT_SAMP + gi] = (gi == TSTEPS-1) ? 1.f : 0.f;
    if (gi == 0) {
        g_arrive = 0;
        dout[OUT_PROBS + 2*(TSTEPS-1) + 0] = 0.f;   // forced last-step probs
        dout[OUT_PROBS + 2*(TSTEPS-1) + 1] = 1.f;
    }
}

// ---- helpers (round-4 verbatim) ----
__device__ __forceinline__ float hdot16(uint4 wa, uint4 wb, uint4 xa, uint4 xb) {
    __half2 h = __hmul2(H2(wa,0), H2(xa,0));
    h = __hfma2(H2(wa,1), H2(xa,1), h);
    h = __hfma2(H2(wa,2), H2(xa,2), h);
    h = __hfma2(H2(wa,3), H2(xa,3), h);
    h = __hfma2(H2(wb,0), H2(xb,0), h);
    h = __hfma2(H2(wb,1), H2(xb,1), h);
    h = __hfma2(H2(wb,2), H2(xb,2), h);
    h = __hfma2(H2(wb,3), H2(xb,3), h);
    return __low2float(h) + __high2float(h);
}

__device__ __forceinline__ float hdot8(uint4 w, uint4 x) {
    __half2 a = __hmul2(H2(w,0), H2(x,0));
    a = __hfma2(H2(w,1), H2(x,1), a);
    a = __hfma2(H2(w,2), H2(x,2), a);
    a = __hfma2(H2(w,3), H2(x,3), a);
    return __low2float(a) + __high2float(a);
}

__device__ __forceinline__ float wredsum(float v) {
    v += __shfl_xor_sync(0xffffffffu, v, 16);
    v += __shfl_xor_sync(0xffffffffu, v, 8);
    v += __shfl_xor_sync(0xffffffffu, v, 4);
    v += __shfl_xor_sync(0xffffffffu, v, 2);
    v += __shfl_xor_sync(0xffffffffu, v, 1);
    return v;
}

__device__ __forceinline__ float sigf(float x) {
    return __fdividef(1.f, 1.f + __expf(-x));
}
__device__ __forceinline__ float tanhfast(float x) {
    return 2.f * sigf(2.f * x) - 1.f;
}

// round-4 gate dots, 16-term fp16 windows. block (g,cp): w + g*GS + cp*64.
template <int NPAIR, int GS, bool RES, bool PF>
__device__ __forceinline__ void gatedot4(const uint4* __restrict__ w,
                                         const uint4* __restrict__ xs, int lane,
                                         const uint4* pw, float* a)
{
#pragma unroll
    for (int cp = 0; cp < NPAIR; ++cp) {
        uint4 xa = xs[cp*64 + lane];
        uint4 xb = xs[cp*64 + 32 + lane];
#pragma unroll
        for (int g = 0; g < 4; ++g) {
            uint4 wa;
            if (PF && cp == 0) wa = pw[g];
            else wa = RES ? w[g*GS + cp*64 + lane] : __ldg(w + g*GS + cp*64 + lane);
            uint4 wb = RES ? w[g*GS + cp*64 + 32 + lane]
                           : __ldg(w + g*GS + cp*64 + 32 + lane);
            a[g] += hdot16(wa, wb, xa, xb);
        }
    }
}

// ---- main persistent kernel: 104 wavefront phases (round-15 verbatim core) ----
__global__ void __launch_bounds__(NTHREADS, 1) k_lstm(
    const float* __restrict__ z,
    const float* __restrict__ bs,
    const float* __restrict__ wp,
    const float* __restrict__ bp,
    float* __restrict__ dout)
{
    extern __shared__ __align__(16) __half smem[];
    __half* s_x = smem + S_X_OFF;

    const int tid  = threadIdx.x;
    const int bid  = blockIdx.x;
    const int wid  = tid >> 5;
    const int lane = tid & 31;
    const bool is_head = (bid == NCTA - 1);

    int u = is_head ? -1 : (wid * NWORK + bid);      // permanent unit ownership
    if (u >= NUNITS) u = -1;
    const int l = (u >= 0) ? (u >> 10) : 0;
    const int j = (u >= 0) ? (u & 1023) : 0;
    const uint4* wr4 = (const uint4*)(g_wpack + (size_t)((u >= 0) ? u : 0) * 4 * ROWLEN);

    const bool res_half = (u >= 0) && (wid == 0);                      // layer-0 Whh half
    const bool res_full = (u >= 0) && (wid >= RES_LO) && (wid <= RES_HI);

    // one-time resident copies
    if (res_half) {
        uint4* dst = (uint4*)smem;
#pragma unroll
        for (int g = 0; g < 4; ++g)
            for (int i = lane; i < 128; i += 32) dst[g*128 + i] = wr4[g*256 + i];
    } else if (res_full) {
        uint4* dst = (uint4*)smem + 512 + (wid - RES_LO) * 1024;
#pragma unroll 4
        for (int i = lane; i < 1024; i += 32) dst[i] = wr4[i];
    }
    const uint4* wsm4 = res_half ? (const uint4*)smem
                      : (const uint4*)smem + 512 + (wid - RES_LO) * 1024;
    __syncthreads();

    // phase-invariant per-warp state
    float b0 = 0.f, b1 = 0.f, b2 = 0.f, b3 = 0.f;
    if (u >= 0) {
        const float* bl = g_bias + l*4096 + j;
        b0 = bl[0]; b1 = bl[1024]; b2 = bl[2048]; b3 = bl[3072];
    }
    float c = 0.f;

    // prefetch chunk-0 weights
    uint4 pw[4];
    auto load_pw = [&]() {
        if (u >= 0) {
            if (res_half) {
#pragma unroll
                for (int g = 0; g < 4; ++g) pw[g] = wsm4[g*128 + lane];
            } else if (res_full) {
#pragma unroll
                for (int g = 0; g < 4; ++g) pw[g] = wsm4[g*256 + lane];
            } else {
#pragma unroll
                for (int g = 0; g < 4; ++g) pw[g] = __ldg(wr4 + g*256 + lane);
            }
        }
    };
    load_pw();

    for (int p = 0; p < NPHASE; ++p) {
        const int rb = (p & 1) ^ 1;
        const int wbuf = p & 1;

        // stage x: [h3|h2|h1|h0], z/zeros at p<=1
        if (tid < 512) {
            int chunk = tid >> 7, k = tid & 127;
            ((uint4*)s_x)[tid] = ((const uint4*)&g_hout[rb][3 - chunk][0])[k];
        } else if (p <= 1 && tid < 640) {
            int k = tid - 512;
            uint4 v;
            if (p == 0) {
                float4 z0 = ((const float4*)z)[k*2];
                float4 z1 = ((const float4*)z)[k*2 + 1];
                __half2 h0 = __floats2half2_rn(z0.x, z0.y);
                __half2 h1 = __floats2half2_rn(z0.z, z0.w);
                __half2 h2 = __floats2half2_rn(z1.x, z1.y);
                __half2 h3 = __floats2half2_rn(z1.z, z1.w);
                v.x = *(unsigned*)&h0; v.y = *(unsigned*)&h1;
                v.z = *(unsigned*)&h2; v.w = *(unsigned*)&h3;
            } else { v.x = v.y = v.z = v.w = 0u; }
            ((uint4*)s_x)[tid] = v;
        }
        __syncthreads();

        if (u >= 0) {
            const int t = p - l;
            if (t >= 0 && t < TSTEPS) {
                float a[4] = {0.f, 0.f, 0.f, 0.f};
                const uint4* xs = (const uint4*)s_x + (3 - l) * 128;
                if (l == 0) {
                    if (t == 0)            // gates = Wih * z (h==0); pw untouched
                        gatedot4<2,256,false,false>(wr4 + 128, (const uint4*)s_x + 512, lane, pw, a);
                    else if (res_half)
                        gatedot4<2,128,true,true>(wsm4, xs, lane, pw, a);
                    else
                        gatedot4<2,256,false,true>(wr4, xs, lane, pw, a);
                } else {
                    if (res_full)
                        gatedot4<4,256,true,true>(wsm4, xs, lane, pw, a);
                    else
                        gatedot4<4,256,false,true>(wr4, xs, lane, pw, a);
                }
                float gi = wredsum(a[0]) + b0;
                float gf = wredsum(a[1]) + b1;
                float gg = wredsum(a[2]) + b2;
                float go = wredsum(a[3]) + b3;
                c = sigf(gf) * c + sigf(gi) * tanhfast(gg);
                float hn = sigf(go) * tanhfast(c);
                if (lane == 0) g_hout[wbuf][l][j] = __float2half_rn(hn);
            }
        } else if (is_head && p >= 4) {
            const int t = p - 4;                       // h_3(t) == s_x[0..127] uint4
            const uint4* xs = (const uint4*)s_x;
            for (int r = wid; r < NST + 2; r += 28) {
                if (r < NST) {
                    const uint4* wrow = (const uint4*)(g_ws + r*NHID);
                    float a = 0.f;
#pragma unroll
                    for (int cch = 0; cch < 4; ++cch)
                        a += hdot8(__ldg(wrow + cch*32 + lane), xs[cch*32 + lane]);
                    a = wredsum(a);
                    if (lane == 0) dout[OUT_STATES + t*NST + r] = a + bs[r];
                } else if (r == NST) {
                    float a0 = 0.f, a1 = 0.f;
#pragma unroll
                    for (int cch = 0; cch < 4; ++cch) {
                        uint4 xv = xs[cch*32 + lane];
                        float2 x0 = __half22float2(H2(xv,0));
                        float2 x1 = __half22float2(H2(xv,1));
                        float2 x2 = __half22float2(H2(xv,2));
                        float2 x3 = __half22float2(H2(xv,3));
                        const float4* p0 = (const float4*)(wp) + cch*64 + lane*2;
                        const float4* p1 = (const float4*)(wp + NHID) + cch*64 + lane*2;
                        float4 wA = p0[0], wB = p0[1];
                        float4 wC = p1[0], wD = p1[1];
                        a0 += wA.x*x0.x + wA.y*x0.y + wA.z*x1.x + wA.w*x1.y
                            + wB.x*x2.x + wB.y*x2.y + wB.z*x3.x + wB.w*x3.y;
                        a1 += wC.x*x0.x + wC.y*x0.y + wC.z*x1.x + wC.w*x1.y
                            + wD.x*x2.x + wD.y*x2.y + wD.z*x3.x + wD.w*x3.y;
                    }
                    a0 = wredsum(a0); a1 = wredsum(a1);
                    if (lane == 0) {
                        float l0v = a0 + bp[0] + 1.0f;   // P_BIAS on logit 0
                        float l1v = a1 + bp[1];
                        float m  = fmaxf(l0v, l1v);
                        float e0 = __expf(l0v - m), e1 = __expf(l1v - m);
                        float inv = 1.f / (e0 + e1);
                        dout[OUT_PROBS + t*2 + 0] = e0 * inv;
                        dout[OUT_PROBS + t*2 + 1] = e1 * inv;
                    }
                }
            }
        }

        // grid barrier (tid0-only arrive + poll, pw prefetch in wait).
        // Final phase: workers only arrive — nothing after depends on others;
        // only the head CTA (epilogue reads h_3(100) from other CTAs) polls.
        __syncthreads();
        if (tid == 0)
            asm volatile("red.release.gpu.global.add.u32 [%0], %1;"
                         :: "l"(&g_arrive), "r"(1u) : "memory");
        load_pw();                       // phase-invariant; fills during the poll
        if (tid == 0 && (p < NPHASE - 1 || is_head)) {
            unsigned target = (unsigned)(p + 1) * NCTA, v;
            do {
                asm volatile("ld.acquire.gpu.global.u32 %0, [%1];"
                             : "=r"(v) : "l"(&g_arrive) : "memory");
            } while (v < target);
        }
        __syncthreads();
    }

    // epilogue: heads for t = 100 (h_3(100) in buffer (NPHASE-1)&1 = 1)
    if (is_head) {
        const uint4* xs = (const uint4*)(&g_hout[1][3][0]);
        for (int r = wid; r < NST; r += 28) {
            const uint4* wrow = (const uint4*)(g_ws + r*NHID);
            float a = 0.f;
#pragma unroll
            for (int cch = 0; cch < 4; ++cch)
                a += hdot8(__ldg(wrow + cch*32 + lane), xs[cch*32 + lane]);
            a = wredsum(a);
            if (lane == 0) dout[OUT_STATES + (TSTEPS-1)*NST + r] = a + bs[r];
        }
    }
}

extern "C" void kernel_launch(void* const* d_in, const int* in_sizes, int n_in,
                              void* d_out, int out_size) {
    (void)in_sizes; (void)n_in; (void)out_size;
    const float* z   = (const float*)d_in[0];
    const float* wih = (const float*)d_in[1];
    const float* whh = (const float*)d_in[2];
    const float* bih = (const float*)d_in[3];
    const float* bhh = (const float*)d_in[4];
    const float* ws  = (const float*)d_in[5];
    const float* bs  = (const float*)d_in[6];
    const float* wp  = (const float*)d_in[7];
    const float* bp  = (const float*)d_in[8];
    float* out = (float*)d_out;

    cudaFuncSetAttribute(k_lstm, cudaFuncAttributeMaxDynamicSharedMemorySize, SMEM_TOTAL);

    k_prep<<<NUNITS*4, 256>>>(wih, whh, bih, bhh, ws, out);
    k_lstm<<<NCTA, NTHREADS, SMEM_TOTAL>>>(z, bs, wp, bp, out);
}